// round 1
// baseline (speedup 1.0000x reference)
#include <cuda_runtime.h>

// out[b] = sum_h sum_k x[b,k]*W[h,k] * (0.5*2.0)
//        = sum_k x[b,k] * S[k],  S[k] = sum_h W[h,k]
// Two HBM-bound passes (~128 MB total). No GEMM needed.

#define BATCH 4096
#define IN    4096
#define HID   4096

__device__ float g_S[IN];  // column sums of W

__global__ void zero_S() {
    int i = blockIdx.x * blockDim.x + threadIdx.x;
    if (i < IN) g_S[i] = 0.0f;
}

// Column-sum of W [HID, IN] row-major.
// grid.x * blockDim.x * 4 == IN ; grid.y splits the HID rows.
__global__ void colsum_kernel(const float* __restrict__ W, int rows_per_block) {
    int k4 = (blockIdx.x * blockDim.x + threadIdx.x);   // float4 index along k
    int k  = k4 * 4;
    int h0 = blockIdx.y * rows_per_block;

    float4 acc = make_float4(0.f, 0.f, 0.f, 0.f);
    const float4* Wv = reinterpret_cast<const float4*>(W);
    int stride4 = IN / 4;

    #pragma unroll 4
    for (int r = 0; r < rows_per_block; r++) {
        float4 v = Wv[(long)(h0 + r) * stride4 + k4];
        acc.x += v.x; acc.y += v.y; acc.z += v.z; acc.w += v.w;
    }
    atomicAdd(&g_S[k + 0], acc.x);
    atomicAdd(&g_S[k + 1], acc.y);
    atomicAdd(&g_S[k + 2], acc.z);
    atomicAdd(&g_S[k + 3], acc.w);
}

// One block per batch row: out[b] = dot(x[b,:], S)
__global__ void matvec_kernel(const float* __restrict__ x, float* __restrict__ out) {
    int b   = blockIdx.x;
    int tid = threadIdx.x;

    const float4* xv = reinterpret_cast<const float4*>(x + (long)b * IN);
    const float4* Sv = reinterpret_cast<const float4*>(g_S);

    // 4 independent accumulators for ILP
    float a0 = 0.f, a1 = 0.f, a2 = 0.f, a3 = 0.f;
    for (int i = tid; i < IN / 4; i += blockDim.x) {
        float4 xx = xv[i];
        float4 ss = Sv[i];
        a0 = fmaf(xx.x, ss.x, a0);
        a1 = fmaf(xx.y, ss.y, a1);
        a2 = fmaf(xx.z, ss.z, a2);
        a3 = fmaf(xx.w, ss.w, a3);
    }
    float sum = (a0 + a1) + (a2 + a3);

    __shared__ float red[256];
    red[tid] = sum;
    __syncthreads();
    for (int s = blockDim.x / 2; s > 0; s >>= 1) {
        if (tid < s) red[tid] += red[tid + s];
        __syncthreads();
    }
    if (tid == 0) out[b] = red[0] * (0.5f * 2.0f);
}

extern "C" void kernel_launch(void* const* d_in, const int* in_sizes, int n_in,
                              void* d_out, int out_size) {
    const float* x = (const float*)d_in[0];
    const float* W = (const float*)d_in[1];
    float* out = (float*)d_out;

    zero_S<<<IN / 256, 256>>>();

    // colsum: blockDim 256, each thread 4 k's -> 1024 k per block -> grid.x = 4
    // grid.y = 128 -> 32 rows per block -> 512 blocks total
    const int rows_per_block = 32;
    dim3 cs_grid(IN / (256 * 4), HID / rows_per_block);
    colsum_kernel<<<cs_grid, 256>>>(W, rows_per_block);

    matvec_kernel<<<BATCH, 256>>>(x, out);
}